// round 6
// baseline (speedup 1.0000x reference)
#include <cuda_runtime.h>
#include <cuda_bf16.h>
#include <cstdint>

#define NN 50000
#define NE 640000
#define F  128
#define NC 16
#define BN_EPS 1e-5f
#define TILES ((NN + 127) / 128)

// ---------------- scratch (__device__ globals; no allocation allowed) ----------------
__device__ int   g_flag64;
__device__ int   g_cnt[NN];
__device__ int   g_cur[NN];
__device__ int   g_rowptr[NN + 1];
__device__ int   g_col[NE];
__device__ float g_dinv[NN];
__device__ float g_h[(size_t)NN * F];
__device__ float g_x[(size_t)NN * F];
__device__ float g_t[(size_t)NN * NC];        // x @ Wf  (N x 16)
__device__ float g_wf[F * NC];                // W2 @ Wc (128 x 16)
__device__ float g_bf[NC];                    // b2 @ Wc + bc
__device__ __nv_bfloat16 g_Bhi[F * F];        // bf16 hi of W1^T  [n][k] row-major
__device__ __nv_bfloat16 g_Blo[F * F];        // bf16 lo of W1^T  [n][k] row-major

// ---------------- edge helpers ----------------
__device__ __forceinline__ void load_edge(const void* ei, int e, int f64, int& s, int& d) {
    if (f64) {
        const long long* p = (const long long*)ei;
        s = (int)p[e];
        d = (int)p[NE + e];
    } else {
        const int* p = (const int*)ei;
        s = p[e];
        d = p[NE + e];
    }
}

// ---------------- prep: W1 split/transpose + fused classifier weights + sniff + zero ----
__global__ void prep_k(const float* __restrict__ W1, const float* __restrict__ W2,
                       const float* __restrict__ Wc, const float* __restrict__ b2,
                       const float* __restrict__ bc, const void* ei) {
    int b = blockIdx.x, t = threadIdx.x;
    if (b < 64) {
        int idx = b * 256 + t;            // idx = n*128 + k  (n = output col)
        int n = idx >> 7, k = idx & 127;
        float w = W1[k * F + n];          // transpose: W1 is [k][n]
        __nv_bfloat16 hi = __float2bfloat16_rn(w);
        float lof = w - __bfloat162float(hi);
        g_Bhi[idx] = hi;
        g_Blo[idx] = __float2bfloat16_rn(lof);
    } else if (b < 72) {
        __shared__ float Wcs[F * NC];
        for (int i = t; i < F * NC; i += 256) Wcs[i] = Wc[i];
        __syncthreads();
        int g = (b - 64) * 256 + t;       // 0..2047
        int i = g >> 4, c = g & 15;
        float acc = 0.f;
        const float* w2r = W2 + (size_t)i * F;
#pragma unroll 8
        for (int k = 0; k < F; k++) acc += w2r[k] * Wcs[k * NC + c];
        g_wf[i * NC + c] = acc;
        if (g < NC) {
            float a = bc[g];
            for (int k = 0; k < F; k++) a += b2[k] * Wcs[k * NC + g];
            g_bf[g] = a;
        }
    } else if (b == 72) {
        if (t == 0) {
            const int* p = (const int*)ei;
            int f = 1;
            for (int i = 0; i < 64; i++)
                if (p[2 * i + 1] != 0) { f = 0; break; }
            g_flag64 = f;
        }
    } else {
        int i = (b - 73) * 256 + t;
        if (i < NN) g_cnt[i] = 0;
    }
}

// ---------------- CSR build ----------------
__global__ void count_k(const void* ei) {
    int e = blockIdx.x * blockDim.x + threadIdx.x;
    int f64 = g_flag64;
    if (e < NE) {
        int s, d;
        load_edge(ei, e, f64, s, d);
        atomicAdd(&g_cnt[d], 1);
    }
}

__global__ void scan_dinv_k() {
    __shared__ int sh[1024];
    const int CH = (NN + 1023) / 1024;  // 49
    int t = threadIdx.x;
    int beg = t * CH;
    int end = beg + CH; if (end > NN) end = NN;
    int s = 0;
    for (int i = beg; i < end; i++) s += g_cnt[i];
    sh[t] = s;
    __syncthreads();
    for (int off = 1; off < 1024; off <<= 1) {
        int v = (t >= off) ? sh[t - off] : 0;
        __syncthreads();
        sh[t] += v;
        __syncthreads();
    }
    int run = (t == 0) ? 0 : sh[t - 1];
    for (int i = beg; i < end; i++) {
        int c = g_cnt[i];
        g_rowptr[i] = run;
        g_cur[i] = run;
        g_dinv[i] = rsqrtf((float)c + 1.0f);  // +1 self loop
        run += c;
    }
    if (t == 0) g_rowptr[NN] = NE;
}

__global__ void fill_k(const void* ei) {
    int e = blockIdx.x * blockDim.x + threadIdx.x;
    int f64 = g_flag64;
    if (e < NE) {
        int s, d;
        load_edge(ei, e, f64, s, d);
        int pos = atomicAdd(&g_cur[d], 1);
        g_col[pos] = s;
    }
}

// ========== tensor-core GEMM1 via mma.sync (bf16 hi/lo split, fp32 acc) ======
// Y[N,128] = X[N,128] @ W1[128,128]; per CTA: 128-row tile, 8 warps (4m x 2n),
// warp tile 32x64. Fragments loaded with plain LDS.32 (K-pairs are contiguous).
#define SA 136                       // padded row stride in bf16 elems (272 B)
#define SAB (SA * 2)                 // 272
#define TILE_B (F * SA * 2)          // 34816 bytes per operand tile
#define S_AHI 0
#define S_ALO (TILE_B)
#define S_BHI (2 * TILE_B)
#define S_BLO (3 * TILE_B)
#define S_TOT (4 * TILE_B)           // 139264 bytes

__device__ __forceinline__ void mma16816(float* c, const uint32_t* a, const uint32_t* b) {
    asm volatile(
        "mma.sync.aligned.m16n8k16.row.col.f32.bf16.bf16.f32 "
        "{%0,%1,%2,%3}, {%4,%5,%6,%7}, {%8,%9}, {%0,%1,%2,%3};"
        : "+f"(c[0]), "+f"(c[1]), "+f"(c[2]), "+f"(c[3])
        : "r"(a[0]), "r"(a[1]), "r"(a[2]), "r"(a[3]), "r"(b[0]), "r"(b[1]));
}

__global__ __launch_bounds__(256, 1) void gemm_mma_k(const float* __restrict__ X,
                                                     float* __restrict__ Y) {
    extern __shared__ char sm[];
    int tid = threadIdx.x;
    int wid = tid >> 5, lane = tid & 31;
    int base = blockIdx.x * 128;

    // ---- stage A (convert fp32 -> bf16 hi/lo) and B (copy) into smem --------
    const float4* X4 = (const float4*)X;
    const uint2* Bh2 = (const uint2*)g_Bhi;   // 4 bf16 per uint2
    const uint2* Bl2 = (const uint2*)g_Blo;
    for (int i = tid; i < 3 * 4096; i += 256) {
        if (i < 4096) {                        // A: row, 4-col group
            int row = i >> 5, c4 = i & 31;
            int gr = base + row;
            float4 v = make_float4(0.f, 0.f, 0.f, 0.f);
            if (gr < NN) v = X4[(size_t)gr * 32 + c4];
            __nv_bfloat162 h01 = __floats2bfloat162_rn(v.x, v.y);
            __nv_bfloat162 h23 = __floats2bfloat162_rn(v.z, v.w);
            __nv_bfloat162 l01 = __floats2bfloat162_rn(v.x - __bfloat162float(h01.x),
                                                       v.y - __bfloat162float(h01.y));
            __nv_bfloat162 l23 = __floats2bfloat162_rn(v.z - __bfloat162float(h23.x),
                                                       v.w - __bfloat162float(h23.y));
            uint32_t boff = row * SAB + c4 * 8;
            *(uint2*)(sm + S_AHI + boff) =
                make_uint2(*(uint32_t*)&h01, *(uint32_t*)&h23);
            *(uint2*)(sm + S_ALO + boff) =
                make_uint2(*(uint32_t*)&l01, *(uint32_t*)&l23);
        } else if (i < 2 * 4096) {             // Bhi
            int j = i - 4096;
            int n = j >> 5, kw = j & 31;
            *(uint2*)(sm + S_BHI + n * SAB + kw * 8) = Bh2[n * 32 + kw];
        } else {                               // Blo
            int j = i - 2 * 4096;
            int n = j >> 5, kw = j & 31;
            *(uint2*)(sm + S_BLO + n * SAB + kw * 8) = Bl2[n * 32 + kw];
        }
    }
    __syncthreads();

    // ---- mainloop: 3 split passes (HH, HL, LH) x 8 K-steps ------------------
    int wm = (wid & 3) * 32;      // warp m offset
    int wn = (wid >> 2) * 64;     // warp n offset
    int rq = lane >> 2;           // 0..7
    int q  = lane & 3;            // 0..3

    float acc[2][8][4];
#pragma unroll
    for (int mt = 0; mt < 2; mt++)
#pragma unroll
        for (int nt = 0; nt < 8; nt++)
#pragma unroll
            for (int e = 0; e < 4; e++) acc[mt][nt][e] = 0.f;

    uint32_t aoff0 = (wm + rq) * SAB + q * 4;   // bytes
    uint32_t boff0 = (wn + rq) * SAB + q * 4;

#pragma unroll
    for (int p = 0; p < 3; p++) {
        const char* Ab = sm + (p == 2 ? S_ALO : S_AHI);
        const char* Bb = sm + (p == 1 ? S_BLO : S_BHI);
#pragma unroll
        for (int ks = 0; ks < 8; ks++) {
            uint32_t ko = ks * 32;  // 16 bf16 = 32 bytes
            uint32_t b[8][2];
#pragma unroll
            for (int nt = 0; nt < 8; nt++) {
                const char* pB = Bb + boff0 + nt * (8 * SAB) + ko;
                b[nt][0] = *(const uint32_t*)(pB);
                b[nt][1] = *(const uint32_t*)(pB + 16);
            }
            uint32_t a[2][4];
#pragma unroll
            for (int mt = 0; mt < 2; mt++) {
                const char* pA = Ab + aoff0 + mt * (16 * SAB) + ko;
                a[mt][0] = *(const uint32_t*)(pA);
                a[mt][1] = *(const uint32_t*)(pA + 8 * SAB);
                a[mt][2] = *(const uint32_t*)(pA + 16);
                a[mt][3] = *(const uint32_t*)(pA + 8 * SAB + 16);
            }
#pragma unroll
            for (int mt = 0; mt < 2; mt++)
#pragma unroll
                for (int nt = 0; nt < 8; nt++)
                    mma16816(acc[mt][nt], a[mt], b[nt]);
        }
    }

    // ---- epilogue: fragment regs -> Y (32B-sector float2 stores) ------------
#pragma unroll
    for (int mt = 0; mt < 2; mt++) {
        int gr0 = base + wm + mt * 16 + rq;
        int gr1 = gr0 + 8;
#pragma unroll
        for (int nt = 0; nt < 8; nt++) {
            int col = wn + nt * 8 + q * 2;
            if (gr0 < NN)
                *(float2*)(Y + (size_t)gr0 * F + col) =
                    make_float2(acc[mt][nt][0], acc[mt][nt][1]);
            if (gr1 < NN)
                *(float2*)(Y + (size_t)gr1 * F + col) =
                    make_float2(acc[mt][nt][2], acc[mt][nt][3]);
        }
    }
}

// ---------------- narrow GEMM: T[N,16] = X[N,128] @ g_wf[128,16] --------------
__global__ void gemm16_k(const float* __restrict__ X, float* __restrict__ T) {
    __shared__ float Ws[F * NC];
    int tid = threadIdx.x;
    for (int i = tid; i < F * NC; i += 256) Ws[i] = g_wf[i];
    __syncthreads();

    int idx = blockIdx.x * 256 + tid;
    if (idx >= NN * NC) return;
    int n = idx >> 4, c = idx & 15;
    float acc = 0.f;
    const float4* xr = (const float4*)(X + (size_t)n * F);
#pragma unroll
    for (int k4 = 0; k4 < 32; k4++) {
        float4 v = xr[k4];
        int kb = k4 * 4;
        acc += v.x * Ws[(kb + 0) * NC + c] + v.y * Ws[(kb + 1) * NC + c] +
               v.z * Ws[(kb + 2) * NC + c] + v.w * Ws[(kb + 3) * NC + c];
    }
    T[idx] = acc;
}

// ---------------- aggregation (128 feats): warp per node, float4 per lane -----
__global__ void agg128_bn_k(const float* __restrict__ h, float* __restrict__ out,
                            const float* __restrict__ bias, const float* __restrict__ gamma,
                            const float* __restrict__ beta, const float* __restrict__ mean,
                            const float* __restrict__ var) {
    int gw = (blockIdx.x * blockDim.x + threadIdx.x) >> 5;
    int lane = threadIdx.x & 31;
    if (gw >= NN) return;
    int n = gw;
    float dn = g_dinv[n];
    const float4* h4 = (const float4*)h;

    float4 acc = h4[(size_t)n * 32 + lane];  // self loop
    float w0 = dn * dn;
    acc.x *= w0; acc.y *= w0; acc.z *= w0; acc.w *= w0;

    int jb = g_rowptr[n], je = g_rowptr[n + 1];
    for (int j = jb; j < je; j++) {
        int s = g_col[j];
        float w = g_dinv[s] * dn;
        float4 v = h4[(size_t)s * 32 + lane];
        acc.x += v.x * w; acc.y += v.y * w; acc.z += v.z * w; acc.w += v.w * w;
    }

    float4 b = ((const float4*)bias)[lane];
    float4 gm = ((const float4*)gamma)[lane];
    float4 bt = ((const float4*)beta)[lane];
    float4 mn = ((const float4*)mean)[lane];
    float4 vr = ((const float4*)var)[lane];
    float4 o;
    o.x = fmaxf(0.f, (acc.x + b.x - mn.x) * rsqrtf(vr.x + BN_EPS) * gm.x + bt.x);
    o.y = fmaxf(0.f, (acc.y + b.y - mn.y) * rsqrtf(vr.y + BN_EPS) * gm.y + bt.y);
    o.z = fmaxf(0.f, (acc.z + b.z - mn.z) * rsqrtf(vr.z + BN_EPS) * gm.z + bt.z);
    o.w = fmaxf(0.f, (acc.w + b.w - mn.w) * rsqrtf(vr.w + BN_EPS) * gm.w + bt.w);
    ((float4*)out)[(size_t)n * 32 + lane] = o;
}

// ---------------- aggregation (16 feats): 4 threads per node ------------------
__global__ void agg16_k(const float* __restrict__ t, float* __restrict__ out) {
    int idx = blockIdx.x * blockDim.x + threadIdx.x;
    int n = idx >> 2;
    int q = idx & 3;
    if (n >= NN) return;
    float dn = g_dinv[n];
    const float4* t4 = (const float4*)t;

    float4 acc = t4[(size_t)n * 4 + q];  // self loop
    float w0 = dn * dn;
    acc.x *= w0; acc.y *= w0; acc.z *= w0; acc.w *= w0;

    int jb = g_rowptr[n], je = g_rowptr[n + 1];
    for (int j = jb; j < je; j++) {
        int s = g_col[j];
        float w = g_dinv[s] * dn;
        float4 v = t4[(size_t)s * 4 + q];
        acc.x += v.x * w; acc.y += v.y * w; acc.z += v.z * w; acc.w += v.w * w;
    }

    float4 b = ((const float4*)g_bf)[q];
    acc.x += b.x; acc.y += b.y; acc.z += b.z; acc.w += b.w;
    ((float4*)out)[(size_t)n * 4 + q] = acc;
}

// ---------------- launch ----------------
extern "C" void kernel_launch(void* const* d_in, const int* in_sizes, int n_in,
                              void* d_out, int out_size) {
    const float* seq   = (const float*)d_in[0];
    const void*  ei    = d_in[1];
    const float* W1    = (const float*)d_in[2];
    const float* b1    = (const float*)d_in[3];
    const float* gamma = (const float*)d_in[4];
    const float* beta  = (const float*)d_in[5];
    const float* rmean = (const float*)d_in[6];
    const float* rvar  = (const float*)d_in[7];
    const float* W2    = (const float*)d_in[8];
    const float* b2    = (const float*)d_in[9];
    const float* Wc    = (const float*)d_in[10];
    const float* bc    = (const float*)d_in[11];
    float* out = (float*)d_out;

    float* gh = nullptr;
    float* gx = nullptr;
    float* gt = nullptr;
    cudaGetSymbolAddress((void**)&gh, g_h);
    cudaGetSymbolAddress((void**)&gx, g_x);
    cudaGetSymbolAddress((void**)&gt, g_t);

    cudaFuncSetAttribute(gemm_mma_k, cudaFuncAttributeMaxDynamicSharedMemorySize, S_TOT);

    // prep (W1 split + fused classifier weights + sniff + zero counts)
    prep_k<<<73 + (NN + 255) / 256, 256>>>(W1, W2, Wc, b2, bc, ei);
    // CSR build
    count_k<<<NE / 256, 256>>>(ei);
    scan_dinv_k<<<1, 1024>>>();
    fill_k<<<NE / 256, 256>>>(ei);

    // layer 1: h = seq @ W1 (mma.sync bf16 split) ; agg + b1 -> BN -> ReLU
    gemm_mma_k<<<TILES, 256, S_TOT>>>(seq, gh);
    agg128_bn_k<<<(NN * 32 + 255) / 256, 256>>>(gh, gx, b1, gamma, beta, rmean, rvar);

    // layer 2 + classifier fused: out = agg(x @ (W2@Wc)) + (b2@Wc + bc)
    gemm16_k<<<(NN * NC + 255) / 256, 256>>>(gx, gt);
    agg16_k<<<(NN * 4 + 255) / 256, 256>>>(gt, out);
}

// round 9
// speedup vs baseline: 1.0618x; 1.0618x over previous
#include <cuda_runtime.h>
#include <cuda_fp16.h>
#include <cstdint>

#define NN 50000
#define NE 640000
#define F  128
#define NC 16
#define BN_EPS 1e-5f

// ---------------- scratch (__device__ globals; no allocation allowed) ----------------
__device__ int    g_flag64;
__device__ int    g_cnt[NN];
__device__ int    g_cur[NN];
__device__ int    g_rowptr[NN + 1];
__device__ int    g_col[NE];
__device__ float  g_dinv[NN];
__device__ __half g_hh[(size_t)NN * F];      // hat-h = dinv * (seq @ W1), fp16
__device__ float  g_x[(size_t)NN * F];       // post-BN/ReLU activations
__device__ float  g_t[(size_t)NN * NC];      // hat-t = dinv * (x @ Wf)
__device__ float  g_wf[F * NC];              // W2 @ Wc (128 x 16)
__device__ float  g_bf[NC];                  // b2 @ Wc + bc

// ---------------- prep: fused classifier weights + sniff + zero counts ----------
// blocks [0,8): Wf = W2 @ Wc, bf = b2 @ Wc + bc
// block 8: edge dtype sniff (int64 vs int32; ids < 50000 => odd words zero iff i64)
// blocks [9, 9+196): zero g_cnt
__global__ void prep_k(const float* __restrict__ W2, const float* __restrict__ Wc,
                       const float* __restrict__ b2, const float* __restrict__ bc,
                       const void* ei) {
    int b = blockIdx.x, t = threadIdx.x;
    if (b < 8) {
        __shared__ float Wcs[F * NC];
        for (int i = t; i < F * NC; i += 256) Wcs[i] = Wc[i];
        __syncthreads();
        int g = b * 256 + t;              // 0..2047
        int i = g >> 4, c = g & 15;
        float acc = 0.f;
        const float* w2r = W2 + (size_t)i * F;
#pragma unroll 8
        for (int k = 0; k < F; k++) acc += w2r[k] * Wcs[k * NC + c];
        g_wf[i * NC + c] = acc;
        if (g < NC) {
            float a = bc[g];
            for (int k = 0; k < F; k++) a += b2[k] * Wcs[k * NC + g];
            g_bf[g] = a;
        }
    } else if (b == 8) {
        if (t == 0) {
            const int* p = (const int*)ei;
            int f = 1;
            for (int i = 0; i < 64; i++)
                if (p[2 * i + 1] != 0) { f = 0; break; }
            g_flag64 = f;
        }
    } else {
        int i = (b - 9) * 256 + t;
        if (i < NN) g_cnt[i] = 0;
    }
}

// ---------------- CSR build (2 edges per thread for MLP) ----------------
__global__ void count_k(const void* ei) {
    int t = blockIdx.x * blockDim.x + threadIdx.x;   // 0 .. NE/2-1
    if (t >= NE / 2) return;
    int d0, d1;
    if (g_flag64) {
        const longlong2* pd = (const longlong2*)((const long long*)ei + NE);
        longlong2 dd = pd[t];
        d0 = (int)dd.x; d1 = (int)dd.y;
    } else {
        const int2* pd = (const int2*)((const int*)ei + NE);
        int2 dd = pd[t];
        d0 = dd.x; d1 = dd.y;
    }
    atomicAdd(&g_cnt[d0], 1);
    atomicAdd(&g_cnt[d1], 1);
}

// single-block exclusive scan of g_cnt -> g_rowptr (+ cursor copy + dinv)
__global__ void scan_dinv_k() {
    __shared__ int sh[1024];
    const int CH = (NN + 1023) / 1024;  // 49
    int t = threadIdx.x;
    int beg = t * CH;
    int end = beg + CH; if (end > NN) end = NN;
    int s = 0;
    for (int i = beg; i < end; i++) s += g_cnt[i];
    sh[t] = s;
    __syncthreads();
    for (int off = 1; off < 1024; off <<= 1) {
        int v = (t >= off) ? sh[t - off] : 0;
        __syncthreads();
        sh[t] += v;
        __syncthreads();
    }
    int run = (t == 0) ? 0 : sh[t - 1];
    for (int i = beg; i < end; i++) {
        int c = g_cnt[i];
        g_rowptr[i] = run;
        g_cur[i] = run;
        g_dinv[i] = rsqrtf((float)c + 1.0f);  // +1 self loop
        run += c;
    }
    if (t == 0) g_rowptr[NN] = NE;
}

__global__ void fill_k(const void* ei) {
    int t = blockIdx.x * blockDim.x + threadIdx.x;   // 0 .. NE/2-1
    if (t >= NE / 2) return;
    int s0, s1, d0, d1;
    if (g_flag64) {
        const longlong2* ps = (const longlong2*)ei;
        const longlong2* pd = (const longlong2*)((const long long*)ei + NE);
        longlong2 ss = ps[t], dd = pd[t];
        s0 = (int)ss.x; s1 = (int)ss.y; d0 = (int)dd.x; d1 = (int)dd.y;
    } else {
        const int2* ps = (const int2*)ei;
        const int2* pd = (const int2*)((const int*)ei + NE);
        int2 ss = ps[t], dd = pd[t];
        s0 = ss.x; s1 = ss.y; d0 = dd.x; d1 = dd.y;
    }
    int p0 = atomicAdd(&g_cur[d0], 1);
    int p1 = atomicAdd(&g_cur[d1], 1);
    g_col[p0] = s0;
    g_col[p1] = s1;
}

// ---------------- dense GEMM: g_hh[N,128] = fp16( dinv * (X[N,128] @ W[128,128]) )
#define GEMM_TM 64
#define XST 132  // padded row stride (floats)

__global__ void gemm_k(const float* __restrict__ X, const float* __restrict__ W,
                       int N) {
    extern __shared__ float sm[];
    float* Ws = sm;                 // [128*128]
    float* Xs = sm + F * F;         // [64 * XST]

    int tid = threadIdx.x;
    const float4* W4 = (const float4*)W;
    float4* Ws4 = (float4*)W4 ? (float4*)Ws : (float4*)Ws;
    for (int i = tid; i < F * F / 4; i += 256) ((float4*)Ws)[i] = W4[i];

    int base = blockIdx.x * GEMM_TM;
    for (int i = tid; i < GEMM_TM * 32; i += 256) {
        int r = i >> 5, c4 = i & 31;
        int gr = base + r;
        float4 v = make_float4(0.f, 0.f, 0.f, 0.f);
        if (gr < N) v = ((const float4*)X)[(size_t)gr * 32 + c4];
        *(float4*)&Xs[r * XST + c4 * 4] = v;
    }
    __syncthreads();

    int colg = tid & 15;
    int rowg = tid >> 4;
    int c0 = colg * 4;
    int r0 = rowg * 4;

    float acc[4][8];
#pragma unroll
    for (int i = 0; i < 4; i++)
#pragma unroll
        for (int j = 0; j < 8; j++) acc[i][j] = 0.f;

#pragma unroll 4
    for (int k = 0; k < F; k++) {
        float x0 = Xs[(r0 + 0) * XST + k];
        float x1 = Xs[(r0 + 1) * XST + k];
        float x2 = Xs[(r0 + 2) * XST + k];
        float x3 = Xs[(r0 + 3) * XST + k];
        float4 wA = *(const float4*)&Ws[k * F + c0];
        float4 wB = *(const float4*)&Ws[k * F + c0 + 64];
        acc[0][0] += x0 * wA.x; acc[0][1] += x0 * wA.y; acc[0][2] += x0 * wA.z; acc[0][3] += x0 * wA.w;
        acc[0][4] += x0 * wB.x; acc[0][5] += x0 * wB.y; acc[0][6] += x0 * wB.z; acc[0][7] += x0 * wB.w;
        acc[1][0] += x1 * wA.x; acc[1][1] += x1 * wA.y; acc[1][2] += x1 * wA.z; acc[1][3] += x1 * wA.w;
        acc[1][4] += x1 * wB.x; acc[1][5] += x1 * wB.y; acc[1][6] += x1 * wB.z; acc[1][7] += x1 * wB.w;
        acc[2][0] += x2 * wA.x; acc[2][1] += x2 * wA.y; acc[2][2] += x2 * wA.z; acc[2][3] += x2 * wA.w;
        acc[2][4] += x2 * wB.x; acc[2][5] += x2 * wB.y; acc[2][6] += x2 * wB.z; acc[2][7] += x2 * wB.w;
        acc[3][0] += x3 * wA.x; acc[3][1] += x3 * wA.y; acc[3][2] += x3 * wA.z; acc[3][3] += x3 * wA.w;
        acc[3][4] += x3 * wB.x; acc[3][5] += x3 * wB.y; acc[3][6] += x3 * wB.z; acc[3][7] += x3 * wB.w;
    }

    uint2* H2 = (uint2*)g_hh;   // 4 halves per uint2; row stride = 32 uint2
#pragma unroll
    for (int i = 0; i < 4; i++) {
        int gr = base + r0 + i;
        if (gr < N) {
            float dv = g_dinv[gr];
            __half2 a0 = __floats2half2_rn(acc[i][0] * dv, acc[i][1] * dv);
            __half2 a1 = __floats2half2_rn(acc[i][2] * dv, acc[i][3] * dv);
            __half2 b0 = __floats2half2_rn(acc[i][4] * dv, acc[i][5] * dv);
            __half2 b1 = __floats2half2_rn(acc[i][6] * dv, acc[i][7] * dv);
            uint2 ua, ub;
            ua.x = *(uint32_t*)&a0; ua.y = *(uint32_t*)&a1;
            ub.x = *(uint32_t*)&b0; ub.y = *(uint32_t*)&b1;
            H2[(size_t)gr * 32 + colg] = ua;
            H2[(size_t)gr * 32 + 16 + colg] = ub;
        }
    }
}

// ---------------- aggregation L1: warp per node, fp16 gather, fused bias+BN+ReLU
// out = relu( (dn*(sum hh[src] + hh[d]) + b1 - mean) * rsqrt(var+eps)*gamma + beta )
__global__ void agg128_bn_k(float* __restrict__ out,
                            const float* __restrict__ bias, const float* __restrict__ gamma,
                            const float* __restrict__ beta, const float* __restrict__ mean,
                            const float* __restrict__ var) {
    int gw = (blockIdx.x * blockDim.x + threadIdx.x) >> 5;
    int lane = threadIdx.x & 31;
    if (gw >= NN) return;
    int n = gw;
    const uint2* H2 = (const uint2*)g_hh;

    uint2 u = H2[(size_t)n * 32 + lane];                       // self loop
    float2 f0 = __half22float2(*reinterpret_cast<__half2*>(&u.x));
    float2 f1 = __half22float2(*reinterpret_cast<__half2*>(&u.y));
    float4 acc = make_float4(f0.x, f0.y, f1.x, f1.y);

    int jb = g_rowptr[n], je = g_rowptr[n + 1];
    for (int j = jb; j < je; j++) {
        int s = g_col[j];
        uint2 v = H2[(size_t)s * 32 + lane];
        float2 a = __half22float2(*reinterpret_cast<__half2*>(&v.x));
        float2 b = __half22float2(*reinterpret_cast<__half2*>(&v.y));
        acc.x += a.x; acc.y += a.y; acc.z += b.x; acc.w += b.y;
    }

    float dn = g_dinv[n];
    float4 b = ((const float4*)bias)[lane];
    float4 gm = ((const float4*)gamma)[lane];
    float4 bt = ((const float4*)beta)[lane];
    float4 mn = ((const float4*)mean)[lane];
    float4 vr = ((const float4*)var)[lane];
    float4 o;
    o.x = fmaxf(0.f, (dn * acc.x + b.x - mn.x) * rsqrtf(vr.x + BN_EPS) * gm.x + bt.x);
    o.y = fmaxf(0.f, (dn * acc.y + b.y - mn.y) * rsqrtf(vr.y + BN_EPS) * gm.y + bt.y);
    o.z = fmaxf(0.f, (dn * acc.z + b.z - mn.z) * rsqrtf(vr.z + BN_EPS) * gm.z + bt.z);
    o.w = fmaxf(0.f, (dn * acc.w + b.w - mn.w) * rsqrtf(vr.w + BN_EPS) * gm.w + bt.w);
    ((float4*)out)[(size_t)n * 32 + lane] = o;
}

// ---------------- narrow GEMM: g_t[n] = dinv[n] * (X[n,:] @ g_wf) --------------
__global__ void gemm16_k(const float* __restrict__ X, float* __restrict__ T) {
    __shared__ float Ws[F * NC];
    int tid = threadIdx.x;
    for (int i = tid; i < F * NC; i += 256) Ws[i] = g_wf[i];
    __syncthreads();

    int idx = blockIdx.x * 256 + tid;
    if (idx >= NN * NC) return;
    int n = idx >> 4, c = idx & 15;
    float acc = 0.f;
    const float4* xr = (const float4*)(X + (size_t)n * F);
#pragma unroll
    for (int k4 = 0; k4 < 32; k4++) {
        float4 v = xr[k4];
        int kb = k4 * 4;
        acc += v.x * Ws[(kb + 0) * NC + c] + v.y * Ws[(kb + 1) * NC + c] +
               v.z * Ws[(kb + 2) * NC + c] + v.w * Ws[(kb + 3) * NC + c];
    }
    T[idx] = acc * g_dinv[n];
}

// ---------------- aggregation L2: 4 threads per node; writes final output ------
// out[d] = dn * (sum t[src] + t[d]) + bf
__global__ void agg16_k(const float* __restrict__ t, float* __restrict__ out) {
    int idx = blockIdx.x * blockDim.x + threadIdx.x;
    int n = idx >> 2;
    int q = idx & 3;
    if (n >= NN) return;
    const float4* t4 = (const float4*)t;

    float4 acc = t4[(size_t)n * 4 + q];  // self loop
    int jb = g_rowptr[n], je = g_rowptr[n + 1];
    for (int j = jb; j < je; j++) {
        int s = g_col[j];
        float4 v = t4[(size_t)s * 4 + q];
        acc.x += v.x; acc.y += v.y; acc.z += v.z; acc.w += v.w;
    }

    float dn = g_dinv[n];
    float4 b = ((const float4*)g_bf)[q];
    acc.x = dn * acc.x + b.x; acc.y = dn * acc.y + b.y;
    acc.z = dn * acc.z + b.z; acc.w = dn * acc.w + b.w;
    ((float4*)out)[(size_t)n * 4 + q] = acc;
}

// ---------------- launch ----------------
extern "C" void kernel_launch(void* const* d_in, const int* in_sizes, int n_in,
                              void* d_out, int out_size) {
    const float* seq   = (const float*)d_in[0];
    const void*  ei    = d_in[1];
    const float* W1    = (const float*)d_in[2];
    const float* b1    = (const float*)d_in[3];
    const float* gamma = (const float*)d_in[4];
    const float* beta  = (const float*)d_in[5];
    const float* rmean = (const float*)d_in[6];
    const float* rvar  = (const float*)d_in[7];
    const float* W2    = (const float*)d_in[8];
    const float* b2    = (const float*)d_in[9];
    const float* Wc    = (const float*)d_in[10];
    const float* bc    = (const float*)d_in[11];
    float* out = (float*)d_out;

    float* gx = nullptr;
    float* gt = nullptr;
    cudaGetSymbolAddress((void**)&gx, g_x);
    cudaGetSymbolAddress((void**)&gt, g_t);

    int smem = (F * F + GEMM_TM * XST) * (int)sizeof(float);  // 99328 bytes
    cudaFuncSetAttribute(gemm_k, cudaFuncAttributeMaxDynamicSharedMemorySize, smem);

    // prep (fused classifier weights + sniff + zero counts)
    prep_k<<<9 + (NN + 255) / 256, 256>>>(W2, Wc, b2, bc, ei);
    // CSR build: 2 edges per thread
    count_k<<<(NE / 2 + 255) / 256, 256>>>(ei);
    scan_dinv_k<<<1, 1024>>>();
    fill_k<<<(NE / 2 + 255) / 256, 256>>>(ei);

    int gemm_blocks = (NN + GEMM_TM - 1) / GEMM_TM;

    // layer 1: hh = fp16(dinv * (seq @ W1)) ; agg -> +b1 -> BN -> ReLU -> g_x
    gemm_k<<<gemm_blocks, 256, smem>>>(seq, W1, NN);
    agg128_bn_k<<<(NN * 32 + 255) / 256, 256>>>(gx, b1, gamma, beta, rmean, rvar);

    // layer 2 + classifier fused: out = dinv*(agg(dinv * (x @ (W2@Wc)))) + (b2@Wc+bc)
    gemm16_k<<<(NN * NC + 255) / 256, 256>>>(gx, gt);
    agg16_k<<<(NN * 4 + 255) / 256, 256>>>(gt, out);
}

// round 10
// speedup vs baseline: 1.0798x; 1.0170x over previous
#include <cuda_runtime.h>
#include <cuda_fp16.h>
#include <cstdint>

#define NN 50000
#define NE 640000
#define F  128
#define NC 16
#define BN_EPS 1e-5f

// ---------------- scratch (__device__ globals; zero-initialized at load) ----------
__device__ int    g_cnt[NN];     // re-zeroed by agg16_k at end of every call
__device__ int    g_cur[NN];
__device__ int    g_rowptr[NN + 1];
__device__ int    g_col[NE];
__device__ float  g_dinv[NN];
__device__ __half g_hh[(size_t)NN * F];      // hat-h = dinv * (seq @ W1), fp16
__device__ float  g_t[(size_t)NN * NC];      // hat-t = dinv * (x @ Wf)
__device__ float  g_wf[F * NC];              // W2 @ Wc (128 x 16)
__device__ float  g_bf[NC];                  // b2 @ Wc + bc

// ---------------- inline edge dtype sniff -------------------------------------
// ids in [0,50000): if int64 (LE), odd int32 words are 0. int32 data has random
// ids there; P(all four == 0) ~ (2e-5)^4 — negligible. First 32B is L1-resident
// after first touch, so this costs ~nothing per thread.
__device__ __forceinline__ int sniff64(const void* ei) {
    const int* p = (const int*)ei;
    return (p[1] | p[3] | p[5] | p[7]) == 0;
}

// ---------------- prep: fused classifier weights + count (4-edge ILP) ----------
// blocks [0,8): Wf = W2 @ Wc, bf = b2 @ Wc + bc
// blocks [8, 8+625): count 4 edges/thread (g_cnt pre-zeroed by prior call / load)
__global__ void prep_k(const float* __restrict__ W2, const float* __restrict__ Wc,
                       const float* __restrict__ b2, const float* __restrict__ bc,
                       const void* ei) {
    int b = blockIdx.x, t = threadIdx.x;
    if (b < 8) {
        __shared__ float Wcs[F * NC];
        for (int i = t; i < F * NC; i += 256) Wcs[i] = Wc[i];
        __syncthreads();
        int g = b * 256 + t;              // 0..2047
        int i = g >> 4, c = g & 15;
        float acc = 0.f;
        const float* w2r = W2 + (size_t)i * F;
#pragma unroll 8
        for (int k = 0; k < F; k++) acc += w2r[k] * Wcs[k * NC + c];
        g_wf[i * NC + c] = acc;
        if (g < NC) {
            float a = bc[g];
            for (int k = 0; k < F; k++) a += b2[k] * Wcs[k * NC + g];
            g_bf[g] = a;
        }
    } else {
        int e4 = (b - 8) * 256 + t;       // 0 .. NE/4-1
        if (e4 >= NE / 4) return;
        int d0, d1, d2, d3;
        if (sniff64(ei)) {
            const longlong2* pd = (const longlong2*)((const long long*)ei + NE);
            longlong2 a = pd[2 * e4], c = pd[2 * e4 + 1];
            d0 = (int)a.x; d1 = (int)a.y; d2 = (int)c.x; d3 = (int)c.y;
        } else {
            const int4* pd = (const int4*)((const int*)ei + NE);
            int4 a = pd[e4];
            d0 = a.x; d1 = a.y; d2 = a.z; d3 = a.w;
        }
        atomicAdd(&g_cnt[d0], 1);
        atomicAdd(&g_cnt[d1], 1);
        atomicAdd(&g_cnt[d2], 1);
        atomicAdd(&g_cnt[d3], 1);
    }
}

// ---------------- single-block scan: rowptr + cursors + dinv ----------------
__global__ void scan_dinv_k() {
    __shared__ int sh[1024];
    const int CH = (NN + 1023) / 1024;  // 49
    int t = threadIdx.x;
    int beg = t * CH;
    int end = beg + CH; if (end > NN) end = NN;
    int s = 0;
    for (int i = beg; i < end; i++) s += g_cnt[i];
    sh[t] = s;
    __syncthreads();
    for (int off = 1; off < 1024; off <<= 1) {
        int v = (t >= off) ? sh[t - off] : 0;
        __syncthreads();
        sh[t] += v;
        __syncthreads();
    }
    int run = (t == 0) ? 0 : sh[t - 1];
    for (int i = beg; i < end; i++) {
        int c = g_cnt[i];
        g_rowptr[i] = run;
        g_cur[i] = run;
        g_dinv[i] = rsqrtf((float)c + 1.0f);  // +1 self loop
        run += c;
    }
    if (t == 0) g_rowptr[NN] = NE;
}

// ---------------- fill: 4 edges/thread, 4 atomics in flight ----------------
__global__ void fill_k(const void* ei) {
    int e4 = blockIdx.x * blockDim.x + threadIdx.x;   // 0 .. NE/4-1
    if (e4 >= NE / 4) return;
    int s0, s1, s2, s3, d0, d1, d2, d3;
    if (sniff64(ei)) {
        const longlong2* ps = (const longlong2*)ei;
        const longlong2* pd = (const longlong2*)((const long long*)ei + NE);
        longlong2 sa = ps[2 * e4], sb = ps[2 * e4 + 1];
        longlong2 da = pd[2 * e4], db = pd[2 * e4 + 1];
        s0 = (int)sa.x; s1 = (int)sa.y; s2 = (int)sb.x; s3 = (int)sb.y;
        d0 = (int)da.x; d1 = (int)da.y; d2 = (int)db.x; d3 = (int)db.y;
    } else {
        const int4* ps = (const int4*)ei;
        const int4* pd = (const int4*)((const int*)ei + NE);
        int4 sa = ps[e4], da = pd[e4];
        s0 = sa.x; s1 = sa.y; s2 = sa.z; s3 = sa.w;
        d0 = da.x; d1 = da.y; d2 = da.z; d3 = da.w;
    }
    int p0 = atomicAdd(&g_cur[d0], 1);
    int p1 = atomicAdd(&g_cur[d1], 1);
    int p2 = atomicAdd(&g_cur[d2], 1);
    int p3 = atomicAdd(&g_cur[d3], 1);
    g_col[p0] = s0;
    g_col[p1] = s1;
    g_col[p2] = s2;
    g_col[p3] = s3;
}

// ---------------- dense GEMM: g_hh = fp16( dinv * (X @ W1) ) ------------------
#define GEMM_TM 64
#define XST 132  // padded row stride (floats)

__global__ void gemm_k(const float* __restrict__ X, const float* __restrict__ W,
                       int N) {
    extern __shared__ float sm[];
    float* Ws = sm;                 // [128*128]
    float* Xs = sm + F * F;         // [64 * XST]

    int tid = threadIdx.x;
    const float4* W4 = (const float4*)W;
    for (int i = tid; i < F * F / 4; i += 256) ((float4*)Ws)[i] = W4[i];

    int base = blockIdx.x * GEMM_TM;
    for (int i = tid; i < GEMM_TM * 32; i += 256) {
        int r = i >> 5, c4 = i & 31;
        int gr = base + r;
        float4 v = make_float4(0.f, 0.f, 0.f, 0.f);
        if (gr < N) v = ((const float4*)X)[(size_t)gr * 32 + c4];
        *(float4*)&Xs[r * XST + c4 * 4] = v;
    }
    __syncthreads();

    int colg = tid & 15;
    int rowg = tid >> 4;
    int c0 = colg * 4;
    int r0 = rowg * 4;

    float acc[4][8];
#pragma unroll
    for (int i = 0; i < 4; i++)
#pragma unroll
        for (int j = 0; j < 8; j++) acc[i][j] = 0.f;

#pragma unroll 4
    for (int k = 0; k < F; k++) {
        float x0 = Xs[(r0 + 0) * XST + k];
        float x1 = Xs[(r0 + 1) * XST + k];
        float x2 = Xs[(r0 + 2) * XST + k];
        float x3 = Xs[(r0 + 3) * XST + k];
        float4 wA = *(const float4*)&Ws[k * F + c0];
        float4 wB = *(const float4*)&Ws[k * F + c0 + 64];
        acc[0][0] += x0 * wA.x; acc[0][1] += x0 * wA.y; acc[0][2] += x0 * wA.z; acc[0][3] += x0 * wA.w;
        acc[0][4] += x0 * wB.x; acc[0][5] += x0 * wB.y; acc[0][6] += x0 * wB.z; acc[0][7] += x0 * wB.w;
        acc[1][0] += x1 * wA.x; acc[1][1] += x1 * wA.y; acc[1][2] += x1 * wA.z; acc[1][3] += x1 * wA.w;
        acc[1][4] += x1 * wB.x; acc[1][5] += x1 * wB.y; acc[1][6] += x1 * wB.z; acc[1][7] += x1 * wB.w;
        acc[2][0] += x2 * wA.x; acc[2][1] += x2 * wA.y; acc[2][2] += x2 * wA.z; acc[2][3] += x2 * wA.w;
        acc[2][4] += x2 * wB.x; acc[2][5] += x2 * wB.y; acc[2][6] += x2 * wB.z; acc[2][7] += x2 * wB.w;
        acc[3][0] += x3 * wA.x; acc[3][1] += x3 * wA.y; acc[3][2] += x3 * wA.z; acc[3][3] += x3 * wA.w;
        acc[3][4] += x3 * wB.x; acc[3][5] += x3 * wB.y; acc[3][6] += x3 * wB.z; acc[3][7] += x3 * wB.w;
    }

    uint2* H2 = (uint2*)g_hh;   // 4 halves per uint2; row stride = 32 uint2
#pragma unroll
    for (int i = 0; i < 4; i++) {
        int gr = base + r0 + i;
        if (gr < N) {
            float dv = g_dinv[gr];
            __half2 a0 = __floats2half2_rn(acc[i][0] * dv, acc[i][1] * dv);
            __half2 a1 = __floats2half2_rn(acc[i][2] * dv, acc[i][3] * dv);
            __half2 b0 = __floats2half2_rn(acc[i][4] * dv, acc[i][5] * dv);
            __half2 b1 = __floats2half2_rn(acc[i][6] * dv, acc[i][7] * dv);
            uint2 ua, ub;
            ua.x = *(uint32_t*)&a0; ua.y = *(uint32_t*)&a1;
            ub.x = *(uint32_t*)&b0; ub.y = *(uint32_t*)&b1;
            H2[(size_t)gr * 32 + colg] = ua;
            H2[(size_t)gr * 32 + 16 + colg] = ub;
        }
    }
}

// ---------------- fused L1-agg + BN + ReLU + (row @ Wf) * dinv -> g_t ---------
// warp per node; 2-edge unroll with dual accumulators for gather MLP.
__global__ void agg128f_k(float* __restrict__ T,
                          const float* __restrict__ bias, const float* __restrict__ gamma,
                          const float* __restrict__ beta, const float* __restrict__ mean,
                          const float* __restrict__ var) {
    __shared__ float Wfs[F * NC];          // 8 KB
    __shared__ float os[8][F];             // per-warp row stash, 4 KB
    int tid = threadIdx.x;
    for (int i = tid; i < F * NC; i += 256) Wfs[i] = g_wf[i];
    __syncthreads();

    int gw = (blockIdx.x * blockDim.x + tid) >> 5;
    int lane = tid & 31;
    int wrp = tid >> 5;
    if (gw >= NN) return;
    int n = gw;
    const uint2* H2 = (const uint2*)g_hh;

    uint2 u = H2[(size_t)n * 32 + lane];                       // self loop
    float2 f0 = __half22float2(*reinterpret_cast<__half2*>(&u.x));
    float2 f1 = __half22float2(*reinterpret_cast<__half2*>(&u.y));
    float4 acc = make_float4(f0.x, f0.y, f1.x, f1.y);
    float4 acc2 = make_float4(0.f, 0.f, 0.f, 0.f);

    int jb = g_rowptr[n], je = g_rowptr[n + 1];
    int j = jb;
    for (; j + 2 <= je; j += 2) {
        int s0 = g_col[j], s1 = g_col[j + 1];
        uint2 v0 = H2[(size_t)s0 * 32 + lane];
        uint2 v1 = H2[(size_t)s1 * 32 + lane];
        float2 a0 = __half22float2(*reinterpret_cast<__half2*>(&v0.x));
        float2 b0 = __half22float2(*reinterpret_cast<__half2*>(&v0.y));
        float2 a1 = __half22float2(*reinterpret_cast<__half2*>(&v1.x));
        float2 b1 = __half22float2(*reinterpret_cast<__half2*>(&v1.y));
        acc.x += a0.x; acc.y += a0.y; acc.z += b0.x; acc.w += b0.y;
        acc2.x += a1.x; acc2.y += a1.y; acc2.z += b1.x; acc2.w += b1.y;
    }
    if (j < je) {
        int s = g_col[j];
        uint2 v = H2[(size_t)s * 32 + lane];
        float2 a = __half22float2(*reinterpret_cast<__half2*>(&v.x));
        float2 b = __half22float2(*reinterpret_cast<__half2*>(&v.y));
        acc.x += a.x; acc.y += a.y; acc.z += b.x; acc.w += b.y;
    }
    acc.x += acc2.x; acc.y += acc2.y; acc.z += acc2.z; acc.w += acc2.w;

    float dn = g_dinv[n];
    float4 b = ((const float4*)bias)[lane];
    float4 gm = ((const float4*)gamma)[lane];
    float4 bt = ((const float4*)beta)[lane];
    float4 mn = ((const float4*)mean)[lane];
    float4 vr = ((const float4*)var)[lane];
    float4 o;
    o.x = fmaxf(0.f, (dn * acc.x + b.x - mn.x) * rsqrtf(vr.x + BN_EPS) * gm.x + bt.x);
    o.y = fmaxf(0.f, (dn * acc.y + b.y - mn.y) * rsqrtf(vr.y + BN_EPS) * gm.y + bt.y);
    o.z = fmaxf(0.f, (dn * acc.z + b.z - mn.z) * rsqrtf(vr.z + BN_EPS) * gm.z + bt.z);
    o.w = fmaxf(0.f, (dn * acc.w + b.w - mn.w) * rsqrtf(vr.w + BN_EPS) * gm.w + bt.w);

    // stash the post-ReLU row in smem (conflict-free), then 16 lanes do the
    // 128-dot per output col with broadcast reads. t-hat = dinv * (o @ Wf).
    *(float4*)&os[wrp][lane * 4] = o;
    __syncwarp();
    if (lane < 16) {
        float pc = 0.f;
#pragma unroll 8
        for (int k4 = 0; k4 < 32; k4++) {
            float4 ov = *(const float4*)&os[wrp][k4 * 4];
            int kb = k4 * 4;
            pc += ov.x * Wfs[(kb + 0) * NC + lane] + ov.y * Wfs[(kb + 1) * NC + lane] +
                  ov.z * Wfs[(kb + 2) * NC + lane] + ov.w * Wfs[(kb + 3) * NC + lane];
        }
        T[(size_t)n * NC + lane] = pc * dn;
    }
}

// ---------------- aggregation L2: 4 threads/node; writes output; re-zeros cnt --
__global__ void agg16_k(const float* __restrict__ t, float* __restrict__ out) {
    int idx = blockIdx.x * blockDim.x + threadIdx.x;
    int n = idx >> 2;
    int q = idx & 3;
    if (n >= NN) return;
    if (q == 0) g_cnt[n] = 0;   // reset for next call (counts already consumed)
    const float4* t4 = (const float4*)t;

    float4 acc = t4[(size_t)n * 4 + q];  // self loop
    float4 acc2 = make_float4(0.f, 0.f, 0.f, 0.f);
    int jb = g_rowptr[n], je = g_rowptr[n + 1];
    int j = jb;
    for (; j + 2 <= je; j += 2) {
        int s0 = g_col[j], s1 = g_col[j + 1];
        float4 v0 = t4[(size_t)s0 * 4 + q];
        float4 v1 = t4[(size_t)s1 * 4 + q];
        acc.x += v0.x; acc.y += v0.y; acc.z += v0.z; acc.w += v0.w;
        acc2.x += v1.x; acc2.y += v1.y; acc2.z += v1.z; acc2.w += v1.w;
    }
    if (j < je) {
        float4 v = t4[(size_t)g_col[j] * 4 + q];
        acc.x += v.x; acc.y += v.y; acc.z += v.z; acc.w += v.w;
    }
    acc.x += acc2.x; acc.y += acc2.y; acc.z += acc2.z; acc.w += acc2.w;

    float dn = g_dinv[n];
    float4 b = ((const float4*)g_bf)[q];
    acc.x = dn * acc.x + b.x; acc.y = dn * acc.y + b.y;
    acc.z = dn * acc.z + b.z; acc.w = dn * acc.w + b.w;
    ((float4*)out)[(size_t)n * 4 + q] = acc;
}

// ---------------- launch (6 kernels) ----------------
extern "C" void kernel_launch(void* const* d_in, const int* in_sizes, int n_in,
                              void* d_out, int out_size) {
    const float* seq   = (const float*)d_in[0];
    const void*  ei    = d_in[1];
    const float* W1    = (const float*)d_in[2];
    const float* b1    = (const float*)d_in[3];
    const float* gamma = (const float*)d_in[4];
    const float* beta  = (const float*)d_in[5];
    const float* rmean = (const float*)d_in[6];
    const float* rvar  = (const float*)d_in[7];
    const float* W2    = (const float*)d_in[8];
    const float* b2    = (const float*)d_in[9];
    const float* Wc    = (const float*)d_in[10];
    const float* bc    = (const float*)d_in[11];
    float* out = (float*)d_out;

    float* gt = nullptr;
    cudaGetSymbolAddress((void**)&gt, g_t);

    int smem = (F * F + GEMM_TM * XST) * (int)sizeof(float);  // 99328 bytes
    cudaFuncSetAttribute(gemm_k, cudaFuncAttributeMaxDynamicSharedMemorySize, smem);

    // prep: Wf fuse + count (g_cnt zeroed by prior call / static init)
    prep_k<<<8 + NE / 4 / 256, 256>>>(W2, Wc, b2, bc, ei);
    scan_dinv_k<<<1, 1024>>>();
    fill_k<<<NE / 4 / 256, 256>>>(ei);

    // layer 1: hh = fp16(dinv * (seq @ W1)); fused agg+BN+ReLU+classifier-proj
    gemm_k<<<(NN + GEMM_TM - 1) / GEMM_TM, 256, smem>>>(seq, W1, NN);
    agg128f_k<<<(NN * 32 + 255) / 256, 256>>>(gt, b1, gamma, beta, rmean, rvar);

    // layer 2 (pre-projected): out = dinv * agg(t-hat) + bf ; also re-zero cnt
    agg16_k<<<(NN * 4 + 255) / 256, 256>>>(gt, out);
}

// round 11
// speedup vs baseline: 1.1048x; 1.0231x over previous
#include <cuda_runtime.h>
#include <cuda_fp16.h>
#include <cstdint>

#define NN 50000
#define NE 640000
#define F  128
#define NC 16
#define BN_EPS 1e-5f

// ---------------- scratch (__device__ globals; zero-initialized at load) ----------
__device__ int    g_cnt[NN];     // re-zeroed by agg16_k at end of every call
__device__ int    g_cur[NN];
__device__ int    g_rowptr[NN + 1];
__device__ int    g_col[NE];
__device__ float  g_dinv[NN];
__device__ __half g_hh[(size_t)NN * F];      // hat-h = dinv * (seq @ W1), fp16
__device__ float  g_t[(size_t)NN * NC];      // hat-t = dinv * (x @ Wf)
__device__ float  g_wf[F * NC];              // W2 @ Wc (128 x 16)
__device__ float  g_bf[NC];                  // b2 @ Wc + bc

// ---------------- inline edge dtype sniff -------------------------------------
// ids in [0,50000): if int64 (LE), odd int32 words are 0. int32 data has random
// ids there; P(all four == 0) ~ (2e-5)^4 — negligible.
__device__ __forceinline__ int sniff64(const void* ei) {
    const int* p = (const int*)ei;
    return (p[1] | p[3] | p[5] | p[7]) == 0;
}

// ---------------- prep: fused classifier weights + count (4-edge ILP) ----------
__global__ void prep_k(const float* __restrict__ W2, const float* __restrict__ Wc,
                       const float* __restrict__ b2, const float* __restrict__ bc,
                       const void* ei) {
    int b = blockIdx.x, t = threadIdx.x;
    if (b < 8) {
        __shared__ float Wcs[F * NC];
        for (int i = t; i < F * NC; i += 256) Wcs[i] = Wc[i];
        __syncthreads();
        int g = b * 256 + t;              // 0..2047
        int i = g >> 4, c = g & 15;
        float acc = 0.f;
        const float* w2r = W2 + (size_t)i * F;
#pragma unroll 8
        for (int k = 0; k < F; k++) acc += w2r[k] * Wcs[k * NC + c];
        g_wf[i * NC + c] = acc;
        if (g < NC) {
            float a = bc[g];
            for (int k = 0; k < F; k++) a += b2[k] * Wcs[k * NC + g];
            g_bf[g] = a;
        }
    } else {
        int e4 = (b - 8) * 256 + t;       // 0 .. NE/4-1
        if (e4 >= NE / 4) return;
        int d0, d1, d2, d3;
        if (sniff64(ei)) {
            const longlong2* pd = (const longlong2*)((const long long*)ei + NE);
            longlong2 a = pd[2 * e4], c = pd[2 * e4 + 1];
            d0 = (int)a.x; d1 = (int)a.y; d2 = (int)c.x; d3 = (int)c.y;
        } else {
            const int4* pd = (const int4*)((const int*)ei + NE);
            int4 a = pd[e4];
            d0 = a.x; d1 = a.y; d2 = a.z; d3 = a.w;
        }
        atomicAdd(&g_cnt[d0], 1);
        atomicAdd(&g_cnt[d1], 1);
        atomicAdd(&g_cnt[d2], 1);
        atomicAdd(&g_cnt[d3], 1);
    }
}

// ---------------- single-block scan: rowptr + cursors + dinv ----------------
__global__ void scan_dinv_k() {
    __shared__ int sh[1024];
    const int CH = (NN + 1023) / 1024;  // 49
    int t = threadIdx.x;
    int beg = t * CH;
    int end = beg + CH; if (end > NN) end = NN;
    int s = 0;
    for (int i = beg; i < end; i++) s += g_cnt[i];
    sh[t] = s;
    __syncthreads();
    for (int off = 1; off < 1024; off <<= 1) {
        int v = (t >= off) ? sh[t - off] : 0;
        __syncthreads();
        sh[t] += v;
        __syncthreads();
    }
    int run = (t == 0) ? 0 : sh[t - 1];
    for (int i = beg; i < end; i++) {
        int c = g_cnt[i];
        g_rowptr[i] = run;
        g_cur[i] = run;
        g_dinv[i] = rsqrtf((float)c + 1.0f);  // +1 self loop
        run += c;
    }
    if (t == 0) g_rowptr[NN] = NE;
}

// ---------------- fill: 4 edges/thread, 4 atomics in flight ----------------
__global__ void fill_k(const void* ei) {
    int e4 = blockIdx.x * blockDim.x + threadIdx.x;   // 0 .. NE/4-1
    if (e4 >= NE / 4) return;
    int s0, s1, s2, s3, d0, d1, d2, d3;
    if (sniff64(ei)) {
        const longlong2* ps = (const longlong2*)ei;
        const longlong2* pd = (const longlong2*)((const long long*)ei + NE);
        longlong2 sa = ps[2 * e4], sb = ps[2 * e4 + 1];
        longlong2 da = pd[2 * e4], db = pd[2 * e4 + 1];
        s0 = (int)sa.x; s1 = (int)sa.y; s2 = (int)sb.x; s3 = (int)sb.y;
        d0 = (int)da.x; d1 = (int)da.y; d2 = (int)db.x; d3 = (int)db.y;
    } else {
        const int4* ps = (const int4*)ei;
        const int4* pd = (const int4*)((const int*)ei + NE);
        int4 sa = ps[e4], da = pd[e4];
        s0 = sa.x; s1 = sa.y; s2 = sa.z; s3 = sa.w;
        d0 = da.x; d1 = da.y; d2 = da.z; d3 = da.w;
    }
    int p0 = atomicAdd(&g_cur[d0], 1);
    int p1 = atomicAdd(&g_cur[d1], 1);
    int p2 = atomicAdd(&g_cur[d2], 1);
    int p3 = atomicAdd(&g_cur[d3], 1);
    g_col[p0] = s0;
    g_col[p1] = s1;
    g_col[p2] = s2;
    g_col[p3] = s3;
}

// ---------------- dense GEMM: g_hh = fp16( dinv * (X @ W1) ) ------------------
// 512 threads, 128x128 tile per CTA (16 warps/SM), float4-vectorized X reads.
#define GEMM_TM 128
#define XST 132  // padded row stride (floats)
#define GEMM_SMEM ((F * F + GEMM_TM * XST) * 4)   // 133120 bytes

__global__ __launch_bounds__(512, 1) void gemm_k(const float* __restrict__ X,
                                                 const float* __restrict__ W, int N) {
    extern __shared__ float sm[];
    float* Ws = sm;                 // [128*128]
    float* Xs = sm + F * F;         // [128 * XST]

    int tid = threadIdx.x;
    const float4* W4 = (const float4*)W;
    for (int i = tid; i < F * F / 4; i += 512) ((float4*)Ws)[i] = W4[i];

    int base = blockIdx.x * GEMM_TM;
    for (int i = tid; i < GEMM_TM * 32; i += 512) {
        int r = i >> 5, c4 = i & 31;
        int gr = base + r;
        float4 v = make_float4(0.f, 0.f, 0.f, 0.f);
        if (gr < N) v = ((const float4*)X)[(size_t)gr * 32 + c4];
        *(float4*)&Xs[r * XST + c4 * 4] = v;
    }
    __syncthreads();

    int colg = tid & 15;            // 0..15 -> cols [c0..c0+3], [c0+64..c0+67]
    int rowg = tid >> 4;            // 0..31 -> rows r0..r0+3
    int c0 = colg * 4;
    int r0 = rowg * 4;

    float acc[4][8];
#pragma unroll
    for (int i = 0; i < 4; i++)
#pragma unroll
        for (int j = 0; j < 8; j++) acc[i][j] = 0.f;

#pragma unroll 4
    for (int k4 = 0; k4 < 32; k4++) {
        float4 xv[4];
#pragma unroll
        for (int i = 0; i < 4; i++)
            xv[i] = *(const float4*)&Xs[(r0 + i) * XST + k4 * 4];
#pragma unroll
        for (int kk = 0; kk < 4; kk++) {
            int k = k4 * 4 + kk;
            float4 wA = *(const float4*)&Ws[k * F + c0];
            float4 wB = *(const float4*)&Ws[k * F + c0 + 64];
            float x0 = (kk == 0) ? xv[0].x : (kk == 1) ? xv[0].y : (kk == 2) ? xv[0].z : xv[0].w;
            float x1 = (kk == 0) ? xv[1].x : (kk == 1) ? xv[1].y : (kk == 2) ? xv[1].z : xv[1].w;
            float x2 = (kk == 0) ? xv[2].x : (kk == 1) ? xv[2].y : (kk == 2) ? xv[2].z : xv[2].w;
            float x3 = (kk == 0) ? xv[3].x : (kk == 1) ? xv[3].y : (kk == 2) ? xv[3].z : xv[3].w;
            acc[0][0] += x0 * wA.x; acc[0][1] += x0 * wA.y; acc[0][2] += x0 * wA.z; acc[0][3] += x0 * wA.w;
            acc[0][4] += x0 * wB.x; acc[0][5] += x0 * wB.y; acc[0][6] += x0 * wB.z; acc[0][7] += x0 * wB.w;
            acc[1][0] += x1 * wA.x; acc[1][1] += x1 * wA.y; acc[1][2] += x1 * wA.z; acc[1][3] += x1 * wA.w;
            acc[1][4] += x1 * wB.x; acc[1][5] += x1 * wB.y; acc[1][6] += x1 * wB.z; acc[1][7] += x1 * wB.w;
            acc[2][0] += x2 * wA.x; acc[2][1] += x2 * wA.y; acc[2][2] += x2 * wA.z; acc[2][3] += x2 * wA.w;
            acc[2][4] += x2 * wB.x; acc[2][5] += x2 * wB.y; acc[2][6] += x2 * wB.z; acc[2][7] += x2 * wB.w;
            acc[3][0] += x3 * wA.x; acc[3][1] += x3 * wA.y; acc[3][2] += x3 * wA.z; acc[3][3] += x3 * wA.w;
            acc[3][4] += x3 * wB.x; acc[3][5] += x3 * wB.y; acc[3][6] += x3 * wB.z; acc[3][7] += x3 * wB.w;
        }
    }

    uint2* H2 = (uint2*)g_hh;   // 4 halves per uint2; row stride = 32 uint2
#pragma unroll
    for (int i = 0; i < 4; i++) {
        int gr = base + r0 + i;
        if (gr < N) {
            float dv = g_dinv[gr];
            __half2 a0 = __floats2half2_rn(acc[i][0] * dv, acc[i][1] * dv);
            __half2 a1 = __floats2half2_rn(acc[i][2] * dv, acc[i][3] * dv);
            __half2 b0 = __floats2half2_rn(acc[i][4] * dv, acc[i][5] * dv);
            __half2 b1 = __floats2half2_rn(acc[i][6] * dv, acc[i][7] * dv);
            uint2 ua, ub;
            ua.x = *(uint32_t*)&a0; ua.y = *(uint32_t*)&a1;
            ub.x = *(uint32_t*)&b0; ub.y = *(uint32_t*)&b1;
            H2[(size_t)gr * 32 + colg] = ua;
            H2[(size_t)gr * 32 + 16 + colg] = ub;
        }
    }
}

// ---------------- fused L1-agg + BN + ReLU + (row @ Wf) * dinv -> g_t ---------
__global__ void agg128f_k(float* __restrict__ T,
                          const float* __restrict__ bias, const float* __restrict__ gamma,
                          const float* __restrict__ beta, const float* __restrict__ mean,
                          const float* __restrict__ var) {
    __shared__ float Wfs[F * NC];          // 8 KB
    __shared__ float os[8][F];             // per-warp row stash, 4 KB
    int tid = threadIdx.x;
    for (int i = tid; i < F * NC; i += 256) Wfs[i] = g_wf[i];
    __syncthreads();

    int gw = (blockIdx.x * blockDim.x + tid) >> 5;
    int lane = tid & 31;
    int wrp = tid >> 5;
    if (gw >= NN) return;
    int n = gw;
    const uint2* H2 = (const uint2*)g_hh;

    uint2 u = H2[(size_t)n * 32 + lane];                       // self loop
    float2 f0 = __half22float2(*reinterpret_cast<__half2*>(&u.x));
    float2 f1 = __half22float2(*reinterpret_cast<__half2*>(&u.y));
    float4 acc = make_float4(f0.x, f0.y, f1.x, f1.y);
    float4 acc2 = make_float4(0.f, 0.f, 0.f, 0.f);

    int jb = g_rowptr[n], je = g_rowptr[n + 1];
    int j = jb;
    for (; j + 2 <= je; j += 2) {
        int s0 = g_col[j], s1 = g_col[j + 1];
        uint2 v0 = H2[(size_t)s0 * 32 + lane];
        uint2 v1 = H2[(size_t)s1 * 32 + lane];
        float2 a0 = __half22float2(*reinterpret_cast<__half2*>(&v0.x));
        float2 b0 = __half22float2(*reinterpret_cast<__half2*>(&v0.y));
        float2 a1 = __half22float2(*reinterpret_cast<__half2*>(&v1.x));
        float2 b1 = __half22float2(*reinterpret_cast<__half2*>(&v1.y));
        acc.x += a0.x; acc.y += a0.y; acc.z += b0.x; acc.w += b0.y;
        acc2.x += a1.x; acc2.y += a1.y; acc2.z += b1.x; acc2.w += b1.y;
    }
    if (j < je) {
        int s = g_col[j];
        uint2 v = H2[(size_t)s * 32 + lane];
        float2 a = __half22float2(*reinterpret_cast<__half2*>(&v.x));
        float2 b = __half22float2(*reinterpret_cast<__half2*>(&v.y));
        acc.x += a.x; acc.y += a.y; acc.z += b.x; acc.w += b.y;
    }
    acc.x += acc2.x; acc.y += acc2.y; acc.z += acc2.z; acc.w += acc2.w;

    float dn = g_dinv[n];
    float4 b = ((const float4*)bias)[lane];
    float4 gm = ((const float4*)gamma)[lane];
    float4 bt = ((const float4*)beta)[lane];
    float4 mn = ((const float4*)mean)[lane];
    float4 vr = ((const float4*)var)[lane];
    float4 o;
    o.x = fmaxf(0.f, (dn * acc.x + b.x - mn.x) * rsqrtf(vr.x + BN_EPS) * gm.x + bt.x);
    o.y = fmaxf(0.f, (dn * acc.y + b.y - mn.y) * rsqrtf(vr.y + BN_EPS) * gm.y + bt.y);
    o.z = fmaxf(0.f, (dn * acc.z + b.z - mn.z) * rsqrtf(vr.z + BN_EPS) * gm.z + bt.z);
    o.w = fmaxf(0.f, (dn * acc.w + b.w - mn.w) * rsqrtf(vr.w + BN_EPS) * gm.w + bt.w);

    *(float4*)&os[wrp][lane * 4] = o;
    __syncwarp();
    if (lane < 16) {
        float pc = 0.f;
#pragma unroll 8
        for (int k4 = 0; k4 < 32; k4++) {
            float4 ov = *(const float4*)&os[wrp][k4 * 4];
            int kb = k4 * 4;
            pc += ov.x * Wfs[(kb + 0) * NC + lane] + ov.y * Wfs[(kb + 1) * NC + lane] +
                  ov.z * Wfs[(kb + 2) * NC + lane] + ov.w * Wfs[(kb + 3) * NC + lane];
        }
        T[(size_t)n * NC + lane] = pc * dn;
    }
}

// ---------------- aggregation L2: 4 threads/node; writes output; re-zeros cnt --
__global__ void agg16_k(const float* __restrict__ t, float* __restrict__ out) {
    int idx = blockIdx.x * blockDim.x + threadIdx.x;
    int n = idx >> 2;
    int q = idx & 3;
    if (n >= NN) return;
    if (q == 0) g_cnt[n] = 0;   // reset for next call (counts already consumed)
    const float4* t4 = (const float4*)t;

    float4 acc = t4[(size_t)n * 4 + q];  // self loop
    float4 acc2 = make_float4(0.f, 0.f, 0.f, 0.f);
    int jb = g_rowptr[n], je = g_rowptr[n + 1];
    int j = jb;
    for (; j + 2 <= je; j += 2) {
        int s0 = g_col[j], s1 = g_col[j + 1];
        float4 v0 = t4[(size_t)s0 * 4 + q];
        float4 v1 = t4[(size_t)s1 * 4 + q];
        acc.x += v0.x; acc.y += v0.y; acc.z += v0.z; acc.w += v0.w;
        acc2.x += v1.x; acc2.y += v1.y; acc2.z += v1.z; acc2.w += v1.w;
    }
    if (j < je) {
        float4 v = t4[(size_t)g_col[j] * 4 + q];
        acc.x += v.x; acc.y += v.y; acc.z += v.z; acc.w += v.w;
    }
    acc.x += acc2.x; acc.y += acc2.y; acc.z += acc2.z; acc.w += acc2.w;

    float dn = g_dinv[n];
    float4 b = ((const float4*)g_bf)[q];
    acc.x = dn * acc.x + b.x; acc.y = dn * acc.y + b.y;
    acc.z = dn * acc.z + b.z; acc.w = dn * acc.w + b.w;
    ((float4*)out)[(size_t)n * 4 + q] = acc;
}

// ---------------- launch (6 kernels) ----------------
extern "C" void kernel_launch(void* const* d_in, const int* in_sizes, int n_in,
                              void* d_out, int out_size) {
    const float* seq   = (const float*)d_in[0];
    const void*  ei    = d_in[1];
    const float* W1    = (const float*)d_in[2];
    const float* b1    = (const float*)d_in[3];
    const float* gamma = (const float*)d_in[4];
    const float* beta  = (const float*)d_in[5];
    const float* rmean = (const float*)d_in[6];
    const float* rvar  = (const float*)d_in[7];
    const float* W2    = (const float*)d_in[8];
    const float* b2    = (const float*)d_in[9];
    const float* Wc    = (const float*)d_in[10];
    const float* bc    = (const float*)d_in[11];
    float* out = (float*)d_out;

    float* gt = nullptr;
    cudaGetSymbolAddress((void**)&gt, g_t);

    cudaFuncSetAttribute(gemm_k, cudaFuncAttributeMaxDynamicSharedMemorySize, GEMM_SMEM);

    // prep: Wf fuse + count (g_cnt zeroed by prior call / static init)
    prep_k<<<8 + NE / 4 / 256, 256>>>(W2, Wc, b2, bc, ei);
    scan_dinv_k<<<1, 1024>>>();
    fill_k<<<NE / 4 / 256, 256>>>(ei);

    // layer 1: hh = fp16(dinv * (seq @ W1)); fused agg+BN+ReLU+classifier-proj
    gemm_k<<<(NN + GEMM_TM - 1) / GEMM_TM, 512, GEMM_SMEM>>>(seq, W1, NN);
    agg128f_k<<<(NN * 32 + 255) / 256, 256>>>(gt, b1, gamma, beta, rmean, rvar);

    // layer 2 (pre-projected): out = dinv * agg(t-hat) + bf ; also re-zero cnt
    agg16_k<<<(NN * 4 + 255) / 256, 256>>>(gt, out);
}